// round 8
// baseline (speedup 1.0000x reference)
#include <cuda_runtime.h>
#include <cuda_bf16.h>
#include <cstdint>

// CRF loss: out[b] = logZ(b) - gold_score(b).  B=2048, L=512, T=32.
// TWO sequences per warp (b, b+1024), interleaved for ILP; lane j owns state j.
// Scaled-prob-space recurrence (Mx = exp(transition), w = exp(emit)):
//   a'[j] = (sum_i a[i]*Mx[i][j]) * w[j] / a_prev[0],   M += log(a_prev[0])
// Mx registers shared by both chains; one __syncwarp serves both per step.

#define CRF_B 2048
#define CRF_L 512
#define CRF_T 32
#define CHUNK 8
#define HALFB (CRF_B / 2)

__device__ __forceinline__ unsigned smem_u32(const void* p) {
    return (unsigned)__cvta_generic_to_shared(p);
}

__global__ __launch_bounds__(32)
void crf_forward_kernel(const float* __restrict__ emit,      // (B, L, T)
                        const float* __restrict__ trans,     // (T, T)
                        const int*   __restrict__ tags,      // (B, L)
                        const int*   __restrict__ lengths,   // (B,)
                        float*       __restrict__ out)       // (B,)
{
    const unsigned FULL = 0xffffffffu;
    __shared__ __align__(16) float ebuf[2][2][CHUNK * CRF_T]; // [chain][buf]
    __shared__ __align__(16) float pbuf[2][2][CRF_T];         // [chain][parity]

    const int lane = threadIdx.x;
    const int b0 = blockIdx.x;
    const int b1 = blockIdx.x + HALFB;
    const int len0 = lengths[b0];
    const int len1 = lengths[b1];

    // Mx column for this lane, packed as 16 f32x2 pairs (shared by both chains).
    unsigned long long Mp[16];
#pragma unroll
    for (int q = 0; q < 16; q++) {
        float m0 = __expf(__ldg(&trans[(2 * q + 0) * CRF_T + lane]));
        float m1 = __expf(__ldg(&trans[(2 * q + 1) * CRF_T + lane]));
        asm("mov.b64 %0, {%1, %2};" : "=l"(Mp[q]) : "f"(m0), "f"(m1));
    }

    const float* erow0 = emit + (size_t)b0 * CRF_L * CRF_T;
    const float* erow1 = emit + (size_t)b1 * CRF_L * CRF_T;
    const int nch0 = (len0 + CHUNK - 1) / CHUNK;
    const int nch1 = (len1 + CHUNK - 1) / CHUNK;
    const int nchmax = nch0 > nch1 ? nch0 : nch1;

    auto issue_chunk = [&](int c) {
        if (c < nch0) {
            const char* src = (const char*)(erow0 + c * (CHUNK * CRF_T));
            unsigned dst = smem_u32(&ebuf[0][c & 1][0]);
            asm volatile("cp.async.cg.shared.global [%0], [%1], 16;\n"
                         :: "r"(dst + lane * 16), "l"(src + lane * 16));
            asm volatile("cp.async.cg.shared.global [%0], [%1], 16;\n"
                         :: "r"(dst + 512 + lane * 16), "l"(src + 512 + lane * 16));
        }
        if (c < nch1) {
            const char* src = (const char*)(erow1 + c * (CHUNK * CRF_T));
            unsigned dst = smem_u32(&ebuf[1][c & 1][0]);
            asm volatile("cp.async.cg.shared.global [%0], [%1], 16;\n"
                         :: "r"(dst + lane * 16), "l"(src + lane * 16));
            asm volatile("cp.async.cg.shared.global [%0], [%1], 16;\n"
                         :: "r"(dst + 512 + lane * 16), "l"(src + 512 + lane * 16));
        }
        asm volatile("cp.async.commit_group;\n");
    };

    issue_chunk(0);
    issue_chunk(1);

    const unsigned pA0 = smem_u32(&pbuf[0][0][0]);
    const unsigned pA1 = smem_u32(&pbuf[0][1][0]);
    const unsigned pB0 = smem_u32(&pbuf[1][0][0]);
    const unsigned pB1 = smem_u32(&pbuf[1][1][0]);

    float a0 = 0.f, a1 = 0.f;     // per-chain alpha (this lane)
    float Ml0 = 0.f, Ml1 = 0.f;   // per-chain running scale, log2

    // One recurrence step: a' = (p . Mxcol) * w / g;  Ml += log2(g)
    auto step = [&](unsigned pin, unsigned pout, float w, float& a, float& Ml) {
        unsigned long long acc0 = 0ull, acc1 = 0ull, x, y;
        float g;
        asm volatile("ld.shared.v2.u64 {%0, %1}, [%2];"
                     : "=l"(x), "=l"(y) : "r"(pin));
        { float ghi;
          asm("mov.b64 {%0, %1}, %2;" : "=f"(g), "=f"(ghi) : "l"(x)); }
        asm("fma.rn.f32x2 %0, %1, %2, %0;" : "+l"(acc0) : "l"(x), "l"(Mp[0]));
        asm("fma.rn.f32x2 %0, %1, %2, %0;" : "+l"(acc1) : "l"(y), "l"(Mp[1]));
#pragma unroll
        for (int q = 1; q < 8; q++) {
            asm volatile("ld.shared.v2.u64 {%0, %1}, [%2];"
                         : "=l"(x), "=l"(y) : "r"(pin + q * 16));
            asm("fma.rn.f32x2 %0, %1, %2, %0;" : "+l"(acc0) : "l"(x), "l"(Mp[2 * q + 0]));
            asm("fma.rn.f32x2 %0, %1, %2, %0;" : "+l"(acc1) : "l"(y), "l"(Mp[2 * q + 1]));
        }
        float rg; asm("rcp.approx.f32 %0, %1;" : "=f"(rg) : "f"(g));
        const float wr = w * rg;
        Ml += __log2f(g);
        asm("add.rn.f32x2 %0, %0, %1;" : "+l"(acc0) : "l"(acc1));
        float s0, s1;
        asm("mov.b64 {%0, %1}, %2;" : "=f"(s0), "=f"(s1) : "l"(acc0));
        a = (s0 + s1) * wr;
        asm volatile("st.shared.f32 [%0], %1;" :: "r"(pout + lane * 4), "f"(a));
    };

    for (int c = 0; c < nchmax; c++) {
        asm volatile("cp.async.wait_group 1;\n" ::: "memory");
        __syncwarp();

        float w0[CHUNK], w1[CHUNK];
        if (c < nch0) {
            const float* E = &ebuf[0][c & 1][0];
#pragma unroll
            for (int k = 0; k < CHUNK; k++) w0[k] = __expf(E[k * CRF_T + lane]);
        }
        if (c < nch1) {
            const float* E = &ebuf[1][c & 1][0];
#pragma unroll
            for (int k = 0; k < CHUNK; k++) w1[k] = __expf(E[k * CRF_T + lane]);
        }

        issue_chunk(c + 2);   // ebuf consumed into w[]; safe to refill

#pragma unroll
        for (int k = 0; k < CHUNK; k++) {
            const int row = c * CHUNK + k;
            if (row == 0) {
                a0 = w0[0]; pbuf[0][0][lane] = a0;   // lengths >= 1 always
                a1 = w1[0]; pbuf[1][0][lane] = a1;
                __syncwarp();
            } else {
                const bool A = row < len0;           // warp-uniform
                const bool B = row < len1;
                const unsigned pinA  = ((row - 1) & 1) ? pA1 : pA0;
                const unsigned poutA = (row & 1)       ? pA1 : pA0;
                const unsigned pinB  = ((row - 1) & 1) ? pB1 : pB0;
                const unsigned poutB = (row & 1)       ? pB1 : pB0;
                if (A) step(pinA, poutA, w0[k], a0, Ml0);
                if (B) step(pinB, poutB, w1[k], a1, Ml1);
                if (A || B) __syncwarp();
            }
        }
    }

    // Epilogue per chain: logZ = Ml*ln2 + log(sum_j a[j]); gold score; output.
#pragma unroll
    for (int g = 0; g < 2; g++) {
        float a   = g ? a1 : a0;
        float Ml  = g ? Ml1 : Ml0;
        int   b   = g ? b1 : b0;
        int   len = g ? len1 : len0;
        const float* erow = g ? erow1 : erow0;

        float sum = a;
#pragma unroll
        for (int off = 16; off; off >>= 1)
            sum += __shfl_xor_sync(FULL, sum, off);
        const float logz = Ml * 0.6931471805599453f + __logf(sum);

        const int* trow = tags + b * CRF_L;
        float gs = 0.f;
        for (int l = lane; l < len; l += 32) {
            int tg = __ldg(&trow[l]);
            gs += __ldg(&erow[l * CRF_T + tg]);
            if (l >= 1) {
                int tp = __ldg(&trow[l - 1]);
                gs += __ldg(&trans[tp * CRF_T + tg]);
            }
        }
#pragma unroll
        for (int off = 16; off; off >>= 1)
            gs += __shfl_xor_sync(FULL, gs, off);

        if (lane == 0) out[b] = logz - gs;
    }
}

extern "C" void kernel_launch(void* const* d_in, const int* in_sizes, int n_in,
                              void* d_out, int out_size)
{
    const float* emit    = (const float*)d_in[0];
    const float* trans   = (const float*)d_in[1];
    const int*   tags    = (const int*)d_in[2];
    const int*   lengths = (const int*)d_in[3];
    float*       out     = (float*)d_out;

    (void)in_sizes; (void)n_in; (void)out_size;

    crf_forward_kernel<<<HALFB, 32>>>(emit, trans, tags, lengths, out);
}

// round 10
// speedup vs baseline: 1.5168x; 1.5168x over previous
#include <cuda_runtime.h>
#include <cuda_bf16.h>
#include <cstdint>

// CRF loss: out[b] = logZ(b) - gold_score(b).  B=2048, L=512, T=32.
// One warp (= one 32-thread block) per batch; lane j owns state j.
// Scaled-prob recurrence (Mx = exp(transition), w = exp(emit)):
//   a'[j] = (sum_i a[i]*Mx[i][j]) * w[j] / a_prev[0],   Ml2 += log2(a_prev[0])
// Cross-lane exchange via smem + BAR.SYNC (nw=1 barrier ~3-7cyc, drains STS;
// much cheaper than WARPSYNC). Gold-path score computed inline per chunk from
// the staged emit tile + smem tags (kills the serial LDG epilogue tail).

#define CRF_B 2048
#define CRF_L 512
#define CRF_T 32
#define CHUNK 8

__device__ __forceinline__ unsigned smem_u32(const void* p) {
    return (unsigned)__cvta_generic_to_shared(p);
}

__global__ __launch_bounds__(32)
void crf_forward_kernel(const float* __restrict__ emit,      // (B, L, T)
                        const float* __restrict__ trans,     // (T, T)
                        const int*   __restrict__ tags,      // (B, L)
                        const int*   __restrict__ lengths,   // (B,)
                        float*       __restrict__ out)       // (B,)
{
    const unsigned FULL = 0xffffffffu;
    __shared__ __align__(16) float ebuf[2][CHUNK * CRF_T];   // staged emit (2x1KB)
    __shared__ __align__(16) float pbuf[2][CRF_T];           // alpha double buffer
    __shared__ __align__(16) int   tbuf[CRF_L];              // this batch's tags

    const int lane = threadIdx.x;
    const int b    = blockIdx.x;
    const int len  = lengths[b];

    // Preload all 512 tags into smem (4 x int4 per lane; beyond len is unused).
    {
        const int4* tg4 = (const int4*)(tags + (size_t)b * CRF_L);
        int4* tb4 = (int4*)tbuf;
#pragma unroll
        for (int i = 0; i < 4; i++)
            tb4[lane + 32 * i] = __ldg(&tg4[lane + 32 * i]);
    }

    // Mx column for this lane, packed as 16 f32x2 pairs over i.
    // (Also warms trans into L1 for the gold-score reads.)
    unsigned long long Mp[16];
#pragma unroll
    for (int q = 0; q < 16; q++) {
        float m0 = __expf(__ldg(&trans[(2 * q + 0) * CRF_T + lane]));
        float m1 = __expf(__ldg(&trans[(2 * q + 1) * CRF_T + lane]));
        asm("mov.b64 %0, {%1, %2};" : "=l"(Mp[q]) : "f"(m0), "f"(m1));
    }

    const float* erow = emit + (size_t)b * CRF_L * CRF_T;
    const int nch = (len + CHUNK - 1) / CHUNK;

    auto issue_chunk = [&](int c) {
        if (c < nch) {
            const char* src = (const char*)(erow + c * (CHUNK * CRF_T));
            unsigned dst = smem_u32(&ebuf[c & 1][0]);
            asm volatile("cp.async.cg.shared.global [%0], [%1], 16;\n"
                         :: "r"(dst + lane * 16), "l"(src + lane * 16));
            asm volatile("cp.async.cg.shared.global [%0], [%1], 16;\n"
                         :: "r"(dst + 512 + lane * 16), "l"(src + 512 + lane * 16));
        }
        asm volatile("cp.async.commit_group;\n");
    };

    issue_chunk(0);
    issue_chunk(1);

    const unsigned pb0 = smem_u32(&pbuf[0][0]);
    const unsigned pb1 = smem_u32(&pbuf[1][0]);

    float a   = 0.f;   // this lane's alpha
    float Ml2 = 0.f;   // running scale, log2
    float gs  = 0.f;   // gold-score partial (lanes 0..7 accumulate)

    __syncthreads();   // tbuf visible to all lanes

    for (int c = 0; c < nch; c++) {
        asm volatile("cp.async.wait_group 1;\n" ::: "memory");
        __syncthreads();
        const float* E = &ebuf[c & 1][0];

        // Off-chain: batched exp of this chunk's emit rows.
        float w[CHUNK];
#pragma unroll
        for (int k = 0; k < CHUNK; k++)
            w[k] = __expf(E[k * CRF_T + lane]);

        // Off-chain: gold-score partials. Lane k<8 handles row r=c*8+k using
        // the staged tile (LDS) + smem tags + L1-hot trans.
        {
            const int r = c * CHUNK + lane;
            if (lane < CHUNK && r < len) {
                const int tg = tbuf[r];
                gs += E[lane * CRF_T + tg];
                if (r >= 1) {
                    const int tp = tbuf[r - 1];
                    gs += __ldg(&trans[tp * CRF_T + tg]);
                }
            }
        }

        issue_chunk(c + 2);   // ebuf consumed; safe to refill

#pragma unroll
        for (int k = 0; k < CHUNK; k++) {
            const int row = c * CHUNK + k;
            if (row == 0) {
                a = w[0];                   // a_0 = exp(e_0), M_0 = 0
                pbuf[0][lane] = a;
                __syncthreads();
            } else if (row < len) {         // warp-uniform predicate
                const unsigned pin  = ((row - 1) & 1) ? pb1 : pb0;
                const unsigned pout = (row & 1)       ? pb1 : pb0;

                unsigned long long A0 = 0ull, A1 = 0ull, A2 = 0ull, A3 = 0ull, x, y;
                float g;
                asm volatile("ld.shared.v2.u64 {%0, %1}, [%2];"
                             : "=l"(x), "=l"(y) : "r"(pin));
                { float hi;
                  asm("mov.b64 {%0, %1}, %2;" : "=f"(g), "=f"(hi) : "l"(x)); }
                asm("fma.rn.f32x2 %0, %1, %2, %0;" : "+l"(A0) : "l"(x), "l"(Mp[0]));
                asm("fma.rn.f32x2 %0, %1, %2, %0;" : "+l"(A1) : "l"(y), "l"(Mp[1]));
#pragma unroll
                for (int q = 1; q < 8; q++) {
                    asm volatile("ld.shared.v2.u64 {%0, %1}, [%2];"
                                 : "=l"(x), "=l"(y) : "r"(pin + q * 16));
                    if (q & 1) {
                        asm("fma.rn.f32x2 %0, %1, %2, %0;" : "+l"(A2) : "l"(x), "l"(Mp[2 * q + 0]));
                        asm("fma.rn.f32x2 %0, %1, %2, %0;" : "+l"(A3) : "l"(y), "l"(Mp[2 * q + 1]));
                    } else {
                        asm("fma.rn.f32x2 %0, %1, %2, %0;" : "+l"(A0) : "l"(x), "l"(Mp[2 * q + 0]));
                        asm("fma.rn.f32x2 %0, %1, %2, %0;" : "+l"(A1) : "l"(y), "l"(Mp[2 * q + 1]));
                    }
                }
                // Off-chain: normalizer reciprocal + scale bookkeeping.
                float rg; asm("rcp.approx.f32 %0, %1;" : "=f"(rg) : "f"(g));
                const float wr = w[k] * rg;
                Ml2 += __log2f(g);
                // Tail: combine 4 accumulators, unpack, scale, publish.
                asm("add.rn.f32x2 %0, %0, %1;" : "+l"(A0) : "l"(A1));
                asm("add.rn.f32x2 %0, %0, %1;" : "+l"(A2) : "l"(A3));
                asm("add.rn.f32x2 %0, %0, %1;" : "+l"(A0) : "l"(A2));
                float s0, s1;
                asm("mov.b64 {%0, %1}, %2;" : "=f"(s0), "=f"(s1) : "l"(A0));
                a = (s0 + s1) * wr;
                asm volatile("st.shared.f32 [%0], %1;" :: "r"(pout + lane * 4), "f"(a));
                __syncthreads();            // BAR nw=1: ~3-7cyc, drains the STS
            }
        }
    }

    // logZ = Ml2*ln2 + log(sum_j a[j])
    float sum = a;
#pragma unroll
    for (int off = 16; off; off >>= 1)
        sum += __shfl_xor_sync(FULL, sum, off);
    const float logz = Ml2 * 0.6931471805599453f + __logf(sum);

    // Gold score: reduce the per-lane partials.
#pragma unroll
    for (int off = 16; off; off >>= 1)
        gs += __shfl_xor_sync(FULL, gs, off);

    if (lane == 0) out[b] = logz - gs;
}

extern "C" void kernel_launch(void* const* d_in, const int* in_sizes, int n_in,
                              void* d_out, int out_size)
{
    const float* emit    = (const float*)d_in[0];
    const float* trans   = (const float*)d_in[1];
    const int*   tags    = (const int*)d_in[2];
    const int*   lengths = (const int*)d_in[3];
    float*       out     = (float*)d_out;

    (void)in_sizes; (void)n_in; (void)out_size;

    crf_forward_kernel<<<CRF_B, 32>>>(emit, trans, tags, lengths, out);
}

// round 11
// speedup vs baseline: 1.6376x; 1.0796x over previous
#include <cuda_runtime.h>
#include <cuda_bf16.h>
#include <cstdint>

// CRF loss: out[b] = logZ(b) - gold_score(b).  B=2048, L=512, T=32.
// Forward/backward split: logZ = LSE_i(alpha_m[i] + beta_m[i]), m = ceil(len/2).
// Block bid<2048: forward alpha over rows [0,m).  bid>=2048: backward beta over
// rows [m,len).  Each is a 32-lane scaled-prob matvec chain (~len/2 steps):
//   fwd: a' = (Mx^T a) * w / a[0]         (Mx = exp(transition), columns/lane)
//   bwd: b' = (Mx (w.b)) / (w.b)[0]       (rows/lane)
// Scales tracked in log2. Partials -> __device__ scratch; combine kernel sums.

#define CRF_B 2048
#define CRF_L 512
#define CRF_T 32
#define CHUNK 8

__device__ float  g_aF[CRF_B * CRF_T];
__device__ float  g_bB[CRF_B * CRF_T];
__device__ float2 g_sF[CRF_B];   // {Ml2_fwd, gold_fwd}
__device__ float2 g_sB[CRF_B];   // {Ml2_bwd, gold_bwd}

__device__ __forceinline__ unsigned smem_u32(const void* p) {
    return (unsigned)__cvta_generic_to_shared(p);
}

__global__ __launch_bounds__(32)
void crf_halves_kernel(const float* __restrict__ emit,      // (B, L, T)
                       const float* __restrict__ trans,     // (T, T)
                       const int*   __restrict__ tags,      // (B, L)
                       const int*   __restrict__ lengths)   // (B,)
{
    const unsigned FULL = 0xffffffffu;
    __shared__ __align__(16) float ebuf[2][CHUNK * CRF_T];
    __shared__ __align__(16) float pbuf[2][CRF_T];
    __shared__ __align__(16) int   tbuf[CRF_L];

    const int  lane = threadIdx.x;
    const bool bwd  = blockIdx.x >= CRF_B;
    const int  b    = bwd ? (blockIdx.x - CRF_B) : blockIdx.x;
    const int  len  = lengths[b];
    const int  m    = (len + 1) >> 1;       // forward rows [0,m), backward [m,len)

    // Tags for this batch (512 ints).
    {
        const int4* tg4 = (const int4*)(tags + (size_t)b * CRF_L);
        int4* tb4 = (int4*)tbuf;
#pragma unroll
        for (int i = 0; i < 4; i++)
            tb4[lane + 32 * i] = __ldg(&tg4[lane + 32 * i]);
    }

    // Transition matrix in exp space, 16 f32x2 pairs per lane.
    // fwd: pairs over i of column lane (Mx[i][lane]).  bwd: pairs over j of row lane.
    unsigned long long Mp[16];
#pragma unroll
    for (int q = 0; q < 16; q++) {
        float m0, m1;
        if (!bwd) {
            m0 = __expf(__ldg(&trans[(2 * q + 0) * CRF_T + lane]));
            m1 = __expf(__ldg(&trans[(2 * q + 1) * CRF_T + lane]));
        } else {
            m0 = __expf(__ldg(&trans[lane * CRF_T + 2 * q + 0]));
            m1 = __expf(__ldg(&trans[lane * CRF_T + 2 * q + 1]));
        }
        asm("mov.b64 %0, {%1, %2};" : "=l"(Mp[q]) : "f"(m0), "f"(m1));
    }

    const float* erow = emit + (size_t)b * CRF_L * CRF_T;
    const unsigned pb0 = smem_u32(&pbuf[0][0]);
    const unsigned pb1 = smem_u32(&pbuf[1][0]);

    float Ml2 = 0.f;
    float gs  = 0.f;

    // Stage chunk c (absolute rows [8c, 8c+8)) into ebuf[c&1].
    auto stage = [&](int c, bool ok) {
        if (ok) {
            const char* src = (const char*)(erow + c * (CHUNK * CRF_T));
            unsigned dst = smem_u32(&ebuf[c & 1][0]);
            asm volatile("cp.async.cg.shared.global [%0], [%1], 16;\n"
                         :: "r"(dst + lane * 16), "l"(src + lane * 16));
            asm volatile("cp.async.cg.shared.global [%0], [%1], 16;\n"
                         :: "r"(dst + 512 + lane * 16), "l"(src + 512 + lane * 16));
        }
        asm volatile("cp.async.commit_group;\n");
    };

    // Shared mat-vec: acc = (pairs from smem[pin]) . Mp ; returns s and g (=vec[0]).
    auto matvec = [&](unsigned pin, float& g) -> float {
        unsigned long long A0 = 0ull, A1 = 0ull, A2 = 0ull, A3 = 0ull, x, y;
        asm volatile("ld.shared.v2.u64 {%0, %1}, [%2];" : "=l"(x), "=l"(y) : "r"(pin));
        { float hi; asm("mov.b64 {%0, %1}, %2;" : "=f"(g), "=f"(hi) : "l"(x)); }
        asm("fma.rn.f32x2 %0, %1, %2, %0;" : "+l"(A0) : "l"(x), "l"(Mp[0]));
        asm("fma.rn.f32x2 %0, %1, %2, %0;" : "+l"(A1) : "l"(y), "l"(Mp[1]));
#pragma unroll
        for (int q = 1; q < 8; q++) {
            asm volatile("ld.shared.v2.u64 {%0, %1}, [%2];"
                         : "=l"(x), "=l"(y) : "r"(pin + q * 16));
            if (q & 1) {
                asm("fma.rn.f32x2 %0, %1, %2, %0;" : "+l"(A2) : "l"(x), "l"(Mp[2 * q + 0]));
                asm("fma.rn.f32x2 %0, %1, %2, %0;" : "+l"(A3) : "l"(y), "l"(Mp[2 * q + 1]));
            } else {
                asm("fma.rn.f32x2 %0, %1, %2, %0;" : "+l"(A0) : "l"(x), "l"(Mp[2 * q + 0]));
                asm("fma.rn.f32x2 %0, %1, %2, %0;" : "+l"(A1) : "l"(y), "l"(Mp[2 * q + 1]));
            }
        }
        asm("add.rn.f32x2 %0, %0, %1;" : "+l"(A0) : "l"(A1));
        asm("add.rn.f32x2 %0, %0, %1;" : "+l"(A2) : "l"(A3));
        asm("add.rn.f32x2 %0, %0, %1;" : "+l"(A0) : "l"(A2));
        float s0, s1;
        asm("mov.b64 {%0, %1}, %2;" : "=f"(s0), "=f"(s1) : "l"(A0));
        return s0 + s1;
    };

    __syncthreads();   // tbuf visible

    if (!bwd) {
        // ---------------- FORWARD: rows [0, m) ----------------
        const int nch = (m + CHUNK - 1) / CHUNK;
        stage(0, 0 < nch);
        stage(1, 1 < nch);
        float a = 0.f;

        for (int c = 0; c < nch; c++) {
            asm volatile("cp.async.wait_group 1;\n" ::: "memory");
            __syncthreads();
            const float* E = &ebuf[c & 1][0];

            float w[CHUNK];
#pragma unroll
            for (int k = 0; k < CHUNK; k++) w[k] = __expf(E[k * CRF_T + lane]);

            {   // gold partials for rows in [0, m)
                const int r = c * CHUNK + lane;
                if (lane < CHUNK && r < m) {
                    const int tg = tbuf[r];
                    gs += E[lane * CRF_T + tg];
                    if (r >= 1) gs += __ldg(&trans[tbuf[r - 1] * CRF_T + tg]);
                }
            }
            stage(c + 2, c + 2 < nch);

#pragma unroll
            for (int k = 0; k < CHUNK; k++) {
                const int row = c * CHUNK + k;
                if (row == 0) {
                    a = w[0];
                    pbuf[0][lane] = a;
                    __syncthreads();
                } else if (row < m) {
                    const unsigned pin  = ((row - 1) & 1) ? pb1 : pb0;
                    const unsigned pout = (row & 1)       ? pb1 : pb0;
                    float g;
                    float s = matvec(pin, g);
                    float rg; asm("rcp.approx.f32 %0, %1;" : "=f"(rg) : "f"(g));
                    Ml2 += __log2f(g);
                    a = s * (w[k] * rg);
                    asm volatile("st.shared.f32 [%0], %1;" :: "r"(pout + lane * 4), "f"(a));
                    __syncthreads();
                }
            }
        }
        g_aF[b * CRF_T + lane] = a;
#pragma unroll
        for (int off = 16; off; off >>= 1) gs += __shfl_xor_sync(FULL, gs, off);
        if (lane == 0) g_sF[b] = make_float2(Ml2, gs);
    } else {
        // ---------------- BACKWARD: rows [m, len), high to low ----------------
        const int cL = (len - 1) >> 3;          // last chunk (has row len-1)
        const int c0 = m >> 3;                  // chunk containing row m
        stage(cL, true);
        stage(cL - 1, cL - 1 >= c0);
        float bta = 1.f;                        // beta_len = 1 (prob space)

        for (int c = cL; c >= c0; c--) {
            asm volatile("cp.async.wait_group 1;\n" ::: "memory");
            __syncthreads();
            const float* E = &ebuf[c & 1][0];

            float w[CHUNK];
#pragma unroll
            for (int k = 0; k < CHUNK; k++) w[k] = __expf(E[k * CRF_T + lane]);

            {   // gold partials for rows in [m, len); r>=m>=1 so transition always
                const int r = c * CHUNK + lane;
                if (lane < CHUNK && r >= m && r < len) {
                    const int tg = tbuf[r];
                    gs += E[lane * CRF_T + tg];
                    gs += __ldg(&trans[tbuf[r - 1] * CRF_T + tg]);
                }
            }
            stage(c - 2, c - 2 >= c0);

#pragma unroll
            for (int k = CHUNK - 1; k >= 0; k--) {
                const int row = c * CHUNK + k;
                if (row >= m && row < len) {
                    // q = w_row * beta ; publish ; matvec with M rows ; renorm by q[0]
                    const float q = w[k] * bta;
                    const unsigned pout = (row & 1) ? pb1 : pb0;
                    asm volatile("st.shared.f32 [%0], %1;" :: "r"(pout + lane * 4), "f"(q));
                    __syncthreads();
                    float g;
                    float s = matvec(pout, g);
                    float rg; asm("rcp.approx.f32 %0, %1;" : "=f"(rg) : "f"(g));
                    Ml2 += __log2f(g);
                    bta = s * rg;
                }
            }
        }
        g_bB[b * CRF_T + lane] = bta;
#pragma unroll
        for (int off = 16; off; off >>= 1) gs += __shfl_xor_sync(FULL, gs, off);
        if (lane == 0) g_sB[b] = make_float2(Ml2, gs);
    }
}

__global__ __launch_bounds__(256)
void crf_combine_kernel(float* __restrict__ out)
{
    const unsigned FULL = 0xffffffffu;
    const int lane = threadIdx.x & 31;
    const int b = (blockIdx.x * blockDim.x + threadIdx.x) >> 5;
    if (b >= CRF_B) return;

    float prod = g_aF[b * CRF_T + lane] * g_bB[b * CRF_T + lane];
#pragma unroll
    for (int off = 16; off; off >>= 1)
        prod += __shfl_xor_sync(FULL, prod, off);

    if (lane == 0) {
        const float2 sF = g_sF[b];
        const float2 sB = g_sB[b];
        const float logz = (sF.x + sB.x) * 0.6931471805599453f + __logf(prod);
        out[b] = logz - (sF.y + sB.y);
    }
}

extern "C" void kernel_launch(void* const* d_in, const int* in_sizes, int n_in,
                              void* d_out, int out_size)
{
    const float* emit    = (const float*)d_in[0];
    const float* trans   = (const float*)d_in[1];
    const int*   tags    = (const int*)d_in[2];
    const int*   lengths = (const int*)d_in[3];
    float*       out     = (float*)d_out;

    (void)in_sizes; (void)n_in; (void)out_size;

    crf_halves_kernel<<<2 * CRF_B, 32>>>(emit, trans, tags, lengths);
    crf_combine_kernel<<<CRF_B * 32 / 256, 256>>>(out);
}